// round 9
// baseline (speedup 1.0000x reference)
#include <cuda_runtime.h>
#include <cstdint>

// Problem constants (fixed-shape instance)
#define BB 16
#define CC 192
#define HH 224
#define WW 224
#define SS 196

#define ROWCHUNKS 16
#define ROWS_PER (HH / ROWCHUNKS)     // 14
#define PIX (ROWS_PER * WW)           // 3136
#define PLANE_BYTES (PIX * 4)         // 12544 (contiguous per channel per chunk)

#define NC 4                          // channels per group
#define NGROUPS (CC / NC)             // 48
#define NSTAGE 2                      // pipeline depth
#define STRIDE PIX                    // 3136
#define GROUP_BYTES (NC * PLANE_BYTES) // 50176
#define NTH 512

// dyn smem layout (bytes):
//   ring      : NSTAGE*NC*STRIDE f32 = 100352
//   sorted_idx: PIX u16              = 6272
//   sorted_seg: PIX u8               = 3136
//   hist      : SS i32               = 784
//   mbars     : NSTAGE u64           = 16
// sort scratch (segtmp PIX i32 + scanbuf NTH i32) overlaid into ring STAGE 1
// (stage 0 is being TMA-filled during the sort; stage 1 untouched until after scatter).
#define RING_FLOATS (NSTAGE * NC * STRIDE)
#define SMEM_BYTES (RING_FLOATS * 4 + PIX * 2 + PIX + SS * 4 + 16)  // 110,560 -> 2 CTAs/SM

__device__ float g_counts[BB * SS];

__device__ __forceinline__ uint32_t smem_u32(const void* p) {
    uint32_t a;
    asm("{ .reg .u64 t; cvta.to.shared.u64 t, %1; cvt.u32.u64 %0, t; }" : "=r"(a) : "l"(p));
    return a;
}
__device__ __forceinline__ void mbar_init(uint32_t mbar, uint32_t cnt) {
    asm volatile("mbarrier.init.shared.b64 [%0], %1;" :: "r"(mbar), "r"(cnt) : "memory");
}
__device__ __forceinline__ void mbar_expect_tx(uint32_t mbar, uint32_t bytes) {
    asm volatile("mbarrier.arrive.expect_tx.shared.b64 _, [%0], %1;" :: "r"(mbar), "r"(bytes) : "memory");
}
__device__ __forceinline__ void mbar_wait(uint32_t mbar, uint32_t parity) {
    asm volatile(
        "{\n\t"
        ".reg .pred P;\n\t"
        "W_%=:\n\t"
        "mbarrier.try_wait.parity.acquire.cta.shared::cta.b64 P, [%0], %1, 0x989680;\n\t"
        "@P bra D_%=;\n\t"
        "bra W_%=;\n\t"
        "D_%=:\n\t"
        "}" :: "r"(mbar), "r"(parity) : "memory");
}
__device__ __forceinline__ void bulk_g2s(uint32_t dst, const void* src, uint32_t bytes, uint32_t mbar) {
    asm volatile("cp.async.bulk.shared::cta.global.mbarrier::complete_tx::bytes [%0], [%1], %2, [%3];"
                 :: "r"(dst), "l"(src), "r"(bytes), "r"(mbar) : "memory");
}

// ---------------- Kernel 1: zero sums (d_out) and counts, vectorized ----------------
__global__ void zero_kernel(float4* __restrict__ out4) {
    const int n4 = BB * SS * CC / 4;   // 150528
    int idx = blockIdx.x * blockDim.x + threadIdx.x;
    if (idx < n4) out4[idx] = make_float4(0.f, 0.f, 0.f, 0.f);
    if (idx < BB * SS) g_counts[idx] = 0.0f;
}

// ---------------- Kernel 2: sort (overlapped with stage-0 fill) + pipelined gather ----------------
// grid: (ROWCHUNKS, 1, BB) = 256 CTAs, block: 512, 2 CTAs/SM -> single wave
__global__ __launch_bounds__(NTH, 2) void accum_kernel(
    const float* __restrict__ feat,   // (B, C, H, W) fp32
    const int* __restrict__ seg,      // (B, H, W) int32
    float* __restrict__ out)          // (B, S, C) fp32 (sums)
{
    extern __shared__ char smem_raw[];
    float* ring = (float*)smem_raw;                                   // NSTAGE*NC*STRIDE f32
    unsigned short* sorted_idx = (unsigned short*)(ring + RING_FLOATS); // PIX u16
    unsigned char*  sorted_seg = (unsigned char*)(sorted_idx + PIX);    // PIX u8
    int* hist = (int*)(sorted_seg + PIX);                             // SS
    unsigned long long* mbars = (unsigned long long*)(hist + SS);     // NSTAGE

    // sort scratch overlaid into ring STAGE 1 (stage 0 is TMA-filling during sort)
    int* segtmp  = (int*)(ring + NC * STRIDE);   // PIX ints (fits in 50KB stage)
    int* scanbuf = segtmp + PIX;                 // NTH ints

    const int tid = threadIdx.x;
    const int b   = blockIdx.z;
    const int h0  = blockIdx.x * ROWS_PER;

    const uint32_t mbar0 = smem_u32(mbars);
    const float* featbase = feat + ((size_t)b * CC * HH + h0) * WW;  // + c*HH*WW
    const size_t plane = (size_t)HH * WW;
    const uint32_t ring_s = smem_u32(ring);

    // mbarrier init + stage-0 TMA issued BEFORE the sort -> fill overlaps sort
    if (tid == 0) {
        #pragma unroll
        for (int s = 0; s < NSTAGE; ++s) mbar_init(mbar0 + 8 * s, 1);
        mbar_expect_tx(mbar0, GROUP_BYTES);
        #pragma unroll
        for (int c = 0; c < NC; ++c) {
            bulk_g2s(ring_s + (uint32_t)(c * STRIDE) * 4,
                     featbase + (size_t)c * plane,
                     PLANE_BYTES, mbar0);
        }
    }

    // ================= Phase 1: counting sort by segment id =================
    for (int i = tid; i < SS; i += NTH) hist[i] = 0;
    __syncthreads();

    const int* segbase = seg + ((size_t)b * HH + h0) * WW;   // contiguous PIX ints
    for (int i = tid; i < PIX; i += NTH) {
        int s = segbase[i];
        s = min(max(s, 0), SS - 1);
        segtmp[i] = s;
        atomicAdd(&hist[s], 1);
    }
    __syncthreads();

    // counts (each CTA owns a unique (b, rowchunk))
    for (int i = tid; i < SS; i += NTH)
        atomicAdd(&g_counts[b * SS + i], (float)hist[i]);

    // block-wide exclusive scan of hist (SS <= NTH)
    int v = (tid < SS) ? hist[tid] : 0;
    scanbuf[tid] = v;
    __syncthreads();
    #pragma unroll
    for (int d = 1; d < NTH; d <<= 1) {
        int t = (tid >= d) ? scanbuf[tid - d] : 0;
        __syncthreads();
        scanbuf[tid] += t;
        __syncthreads();
    }
    if (tid < SS) hist[tid] = scanbuf[tid] - v;  // exclusive start offsets
    __syncthreads();

    // scatter
    for (int i = tid; i < PIX; i += NTH) {
        int s = segtmp[i];
        int pos = atomicAdd(&hist[s], 1);
        sorted_idx[pos] = (unsigned short)i;
        sorted_seg[pos] = (unsigned char)s;
    }
    __syncthreads();   // sort done; stage-1 scratch dead -> issue stage-1 TMA

    if (tid == 0) {
        mbar_expect_tx(mbar0 + 8, GROUP_BYTES);
        #pragma unroll
        for (int c = 0; c < NC; ++c) {
            bulk_g2s(ring_s + (uint32_t)((NC + c) * STRIDE) * 4,
                     featbase + (size_t)(NC + c) * plane,
                     PLANE_BYTES, mbar0 + 8);
        }
    }

    // ================= Phase 2: pipelined channel groups =================

    // exact 7/6 partition: threads 0..63 handle 7 entries, 64..511 handle 6
    const bool has7 = (tid < 64);
    const int base  = has7 ? tid * 7 : tid * 6 + 64;

    // register-cached window: eidx[j] = pixel idx, eflush[j] = (prev_s*CC)<<1 | boundary
    int eidx[7];
    int eflush[7];
    int last_off;
    {
        int prev_s = -1;
        #pragma unroll
        for (int j = 0; j < 7; ++j) {
            int jj = base + ((j == 6 && !has7) ? 5 : j);  // replicate (unused) for 6-entry threads
            int ij = sorted_idx[jj];
            int sj = sorted_seg[jj];
            eidx[j] = ij;
            int nb = (j > 0 && sj != prev_s) ? 1 : 0;
            eflush[j] = ((prev_s < 0 ? 0 : prev_s * CC) << 1) | nb;
            prev_s = sj;
        }
        last_off = prev_s * CC;
    }

    float* obase0 = out + (size_t)b * SS * CC;

    for (int g = 0; g < NGROUPS; ++g) {
        const int st = g & 1;
        const uint32_t mb = mbar0 + 8 * st;
        mbar_wait(mb, (g >> 1) & 1);

        const float* p0 = ring + (st * NC + 0) * STRIDE;
        const float* p1 = ring + (st * NC + 1) * STRIDE;
        const float* p2 = ring + (st * NC + 2) * STRIDE;
        const float* p3 = ring + (st * NC + 3) * STRIDE;
        float* obase = obase0 + g * NC;

        float a0 = 0.f, a1 = 0.f, a2 = 0.f, a3 = 0.f;

        #define STEP(j)                                                            \
        {                                                                          \
            int e  = eidx[j];                                                      \
            float v0 = p0[e], v1 = p1[e], v2 = p2[e], v3 = p3[e];                  \
            int fo = eflush[j];                                                    \
            float* oaddr = obase + (fo >> 1);                                      \
            asm volatile(                                                          \
                "{ .reg .pred p; setp.ne.s32 p, %0, 0;\n\t"                        \
                "@p red.global.add.v4.f32 [%1], {%2,%3,%4,%5}; }"                  \
                :: "r"(fo & 1), "l"(oaddr),                                        \
                   "f"(a0), "f"(a1), "f"(a2), "f"(a3) : "memory");                 \
            bool nb = (fo & 1);                                                    \
            a0 = nb ? v0 : a0 + v0;                                                \
            a1 = nb ? v1 : a1 + v1;                                                \
            a2 = nb ? v2 : a2 + v2;                                                \
            a3 = nb ? v3 : a3 + v3;                                                \
        }

        STEP(0) STEP(1) STEP(2) STEP(3) STEP(4) STEP(5)
        if (has7) { STEP(6) }   // warp-uniform (warps 0,1 only)
        #undef STEP

        __syncthreads();   // all gathers on buffer st complete before refill

        if (tid == 0 && g + NSTAGE < NGROUPS) {
            const int gn = g + NSTAGE;
            mbar_expect_tx(mb, GROUP_BYTES);
            #pragma unroll
            for (int c = 0; c < NC; ++c) {
                bulk_g2s(ring_s + (uint32_t)((st * NC + c) * STRIDE) * 4,
                         featbase + (size_t)(gn * NC + c) * plane,
                         PLANE_BYTES, mb);
            }
        }

        // final flush AFTER refill issuance (REDG independent of ring; TMA starts earlier)
        asm volatile("red.global.add.v4.f32 [%0], {%1,%2,%3,%4};"
                     :: "l"(obase + last_off), "f"(a0), "f"(a1), "f"(a2), "f"(a3)
                     : "memory");
    }
}

// ---------------- Kernel 3: finalize, vectorized (divide by count, add positional) ----------------
__global__ void finalize_kernel(
    float4* __restrict__ out4,                 // (B, S, C/4) sums -> final
    const float* __restrict__ centroid,        // (B, S, 2)
    const float4* __restrict__ posW4,          // (2, C/4)
    const float4* __restrict__ posb4)          // (C/4,)
{
    const int C4 = CC / 4;
    int idx = blockIdx.x * blockDim.x + threadIdx.x;
    if (idx >= BB * SS * C4) return;
    int c4 = idx % C4;
    int bs = idx / C4;
    float inv = 1.0f / fmaxf(g_counts[bs], 1.0f);
    float cx = centroid[bs * 2 + 0] * (1.0f / WW);
    float cy = centroid[bs * 2 + 1] * (1.0f / HH);
    float4 w0 = posW4[c4];
    float4 w1 = posW4[C4 + c4];
    float4 bb = posb4[c4];
    float4 s = out4[idx];
    s.x = s.x * inv + fmaf(cx, w0.x, fmaf(cy, w1.x, bb.x));
    s.y = s.y * inv + fmaf(cx, w0.y, fmaf(cy, w1.y, bb.y));
    s.z = s.z * inv + fmaf(cx, w0.z, fmaf(cy, w1.z, bb.z));
    s.w = s.w * inv + fmaf(cx, w0.w, fmaf(cy, w1.w, bb.w));
    out4[idx] = s;
}

extern "C" void kernel_launch(void* const* d_in, const int* in_sizes, int n_in,
                              void* d_out, int out_size)
{
    // inputs: 0=img(unused) 1=features 2=segments(int32) 3=centroid_coords 4=pos_W 5=pos_b 6=max_segments
    const float* feat     = (const float*)d_in[1];
    const int*   seg      = (const int*)d_in[2];
    const float* centroid = (const float*)d_in[3];
    const float* posW     = (const float*)d_in[4];
    const float* posb     = (const float*)d_in[5];
    float* out = (float*)d_out;

    (void)in_sizes; (void)n_in; (void)out_size;

    static bool attr_set = false;
    if (!attr_set) {
        cudaFuncSetAttribute(accum_kernel,
                             cudaFuncAttributeMaxDynamicSharedMemorySize, SMEM_BYTES);
        attr_set = true;
    }

    const int n4 = BB * SS * CC / 4;
    zero_kernel<<<(n4 + 255) / 256, 256>>>((float4*)out);

    dim3 grid(ROWCHUNKS, 1, BB);
    accum_kernel<<<grid, NTH, SMEM_BYTES>>>(feat, seg, out);

    finalize_kernel<<<(n4 + 255) / 256, 256>>>((float4*)out, centroid,
                                               (const float4*)posW, (const float4*)posb);
}

// round 11
// speedup vs baseline: 1.0751x; 1.0751x over previous
#include <cuda_runtime.h>
#include <cstdint>

// Problem constants (fixed-shape instance)
#define BB 16
#define CC 192
#define HH 224
#define WW 224
#define SS 196

#define ROWCHUNKS 16
#define ROWS_PER (HH / ROWCHUNKS)     // 14
#define PIX (ROWS_PER * WW)           // 3136
#define PLANE_BYTES (PIX * 4)         // 12544 (contiguous per channel per chunk)

#define NC 4                          // channels per group
#define NGROUPS (CC / NC)             // 48
#define NSTAGE 2                      // pipeline depth
#define STRIDE PIX                    // 3136
#define GROUP_BYTES (NC * PLANE_BYTES) // 50176
#define NTH 512

// dyn smem layout (bytes):
//   ring      : NSTAGE*NC*STRIDE f32 = 100352
//   sorted_idx: PIX u16              = 6272
//   sorted_seg: PIX u8               = 3136
//   hist      : SS i32               = 784
//   mbars     : NSTAGE u64           = 16
// sort scratch (segtmp PIX i32 + scanbuf NTH i32) overlaid into ring.
#define RING_FLOATS (NSTAGE * NC * STRIDE)
#define SMEM_BYTES (RING_FLOATS * 4 + PIX * 2 + PIX + SS * 4 + 16)  // 110,560 -> 2 CTAs/SM

__device__ float g_counts[BB * SS];

__device__ __forceinline__ uint32_t smem_u32(const void* p) {
    uint32_t a;
    asm("{ .reg .u64 t; cvta.to.shared.u64 t, %1; cvt.u32.u64 %0, t; }" : "=r"(a) : "l"(p));
    return a;
}
__device__ __forceinline__ void mbar_init(uint32_t mbar, uint32_t cnt) {
    asm volatile("mbarrier.init.shared.b64 [%0], %1;" :: "r"(mbar), "r"(cnt) : "memory");
}
__device__ __forceinline__ void mbar_expect_tx(uint32_t mbar, uint32_t bytes) {
    asm volatile("mbarrier.arrive.expect_tx.shared.b64 _, [%0], %1;" :: "r"(mbar), "r"(bytes) : "memory");
}
__device__ __forceinline__ void mbar_wait(uint32_t mbar, uint32_t parity) {
    asm volatile(
        "{\n\t"
        ".reg .pred P;\n\t"
        "W_%=:\n\t"
        "mbarrier.try_wait.parity.acquire.cta.shared::cta.b64 P, [%0], %1, 0x989680;\n\t"
        "@P bra D_%=;\n\t"
        "bra W_%=;\n\t"
        "D_%=:\n\t"
        "}" :: "r"(mbar), "r"(parity) : "memory");
}
__device__ __forceinline__ void bulk_g2s(uint32_t dst, const void* src, uint32_t bytes, uint32_t mbar) {
    asm volatile("cp.async.bulk.shared::cta.global.mbarrier::complete_tx::bytes [%0], [%1], %2, [%3];"
                 :: "r"(dst), "l"(src), "r"(bytes), "r"(mbar) : "memory");
}

// ---------------- Kernel 1: zero sums (d_out) and counts, vectorized ----------------
__global__ void zero_kernel(float4* __restrict__ out4) {
    const int n4 = BB * SS * CC / 4;   // 150528
    int idx = blockIdx.x * blockDim.x + threadIdx.x;
    if (idx < n4) out4[idx] = make_float4(0.f, 0.f, 0.f, 0.f);
    if (idx < BB * SS) g_counts[idx] = 0.0f;
}

// ---------------- Kernel 2: sort once + pipelined gather, register-cached entries ----------------
// grid: (ROWCHUNKS, 1, BB) = 256 CTAs, block: 512, 2 CTAs/SM -> single wave
__global__ __launch_bounds__(NTH, 2) void accum_kernel(
    const float* __restrict__ feat,   // (B, C, H, W) fp32
    const int* __restrict__ seg,      // (B, H, W) int32
    float* __restrict__ out)          // (B, S, C) fp32 (sums)
{
    extern __shared__ char smem_raw[];
    float* ring = (float*)smem_raw;                                   // NSTAGE*NC*STRIDE f32
    unsigned short* sorted_idx = (unsigned short*)(ring + RING_FLOATS); // PIX u16
    unsigned char*  sorted_seg = (unsigned char*)(sorted_idx + PIX);    // PIX u8
    int* hist = (int*)(sorted_seg + PIX);                             // SS
    unsigned long long* mbars = (unsigned long long*)(hist + SS);     // NSTAGE

    // sort scratch overlaid into ring (dead before TMA starts)
    int* segtmp  = (int*)ring;        // PIX ints
    int* scanbuf = segtmp + PIX;      // NTH ints

    const int tid = threadIdx.x;
    const int b   = blockIdx.z;
    const int h0  = blockIdx.x * ROWS_PER;

    const uint32_t mbar0 = smem_u32(mbars);

    if (tid == 0) {
        #pragma unroll
        for (int s = 0; s < NSTAGE; ++s) mbar_init(mbar0 + 8 * s, 1);
    }

    // ================= Phase 1: counting sort by segment id =================
    for (int i = tid; i < SS; i += NTH) hist[i] = 0;
    __syncthreads();

    const int* segbase = seg + ((size_t)b * HH + h0) * WW;   // contiguous PIX ints
    for (int i = tid; i < PIX; i += NTH) {
        int s = segbase[i];
        s = min(max(s, 0), SS - 1);
        segtmp[i] = s;
        atomicAdd(&hist[s], 1);
    }
    __syncthreads();

    // counts (each CTA owns a unique (b, rowchunk))
    for (int i = tid; i < SS; i += NTH)
        atomicAdd(&g_counts[b * SS + i], (float)hist[i]);

    // block-wide exclusive scan of hist (SS <= NTH)
    int v = (tid < SS) ? hist[tid] : 0;
    scanbuf[tid] = v;
    __syncthreads();
    #pragma unroll
    for (int d = 1; d < NTH; d <<= 1) {
        int t = (tid >= d) ? scanbuf[tid - d] : 0;
        __syncthreads();
        scanbuf[tid] += t;
        __syncthreads();
    }
    if (tid < SS) hist[tid] = scanbuf[tid] - v;  // exclusive start offsets
    __syncthreads();

    // scatter
    for (int i = tid; i < PIX; i += NTH) {
        int s = segtmp[i];
        int pos = atomicAdd(&hist[s], 1);
        sorted_idx[pos] = (unsigned short)i;
        sorted_seg[pos] = (unsigned char)s;
    }
    __syncthreads();   // sort done; ring scratch dead -> safe for TMA

    // ================= Phase 2: pipelined channel groups =================
    const float* featbase = feat + ((size_t)b * CC * HH + h0) * WW;  // + c*HH*WW
    const size_t plane = (size_t)HH * WW;
    const uint32_t ring_s = smem_u32(ring);

    // prologue: issue TMAs for groups 0..NSTAGE-1
    if (tid == 0) {
        #pragma unroll
        for (int s = 0; s < NSTAGE; ++s) {
            mbar_expect_tx(mbar0 + 8 * s, GROUP_BYTES);
            #pragma unroll
            for (int c = 0; c < NC; ++c) {
                bulk_g2s(ring_s + (uint32_t)((s * NC + c) * STRIDE) * 4,
                         featbase + (size_t)(s * NC + c) * plane,
                         PLANE_BYTES, mbar0 + 8 * s);
            }
        }
    }

    // exact 7/6 partition: threads 0..63 handle 7 entries, 64..511 handle 6
    //   64*7 + 448*6 = 3136 = PIX
    const bool has7 = (tid < 64);
    const int base  = has7 ? tid * 7 : tid * 6 + 64;

    // register-cached window: eidx[j] = pixel idx, eflush[j] = (prev_s*CC)<<1 | boundary
    int eidx[7];
    int eflush[7];
    int last_off;
    {
        int prev_s = -1;
        #pragma unroll
        for (int j = 0; j < 7; ++j) {
            int jj = base + ((j == 6 && !has7) ? 5 : j);  // replicate (unused) for 6-entry threads
            int ij = sorted_idx[jj];
            int sj = sorted_seg[jj];
            eidx[j] = ij;
            int nb = (j > 0 && sj != prev_s) ? 1 : 0;
            eflush[j] = ((prev_s < 0 ? 0 : prev_s * CC) << 1) | nb;
            prev_s = sj;
        }
        last_off = prev_s * CC;
    }

    float* obase0 = out + (size_t)b * SS * CC;

    for (int g = 0; g < NGROUPS; ++g) {
        const int st = g & 1;
        const uint32_t mb = mbar0 + 8 * st;
        mbar_wait(mb, (g >> 1) & 1);

        const float* p0 = ring + (st * NC + 0) * STRIDE;
        const float* p1 = ring + (st * NC + 1) * STRIDE;
        const float* p2 = ring + (st * NC + 2) * STRIDE;
        const float* p3 = ring + (st * NC + 3) * STRIDE;
        float* obase = obase0 + g * NC;

        float a0 = 0.f, a1 = 0.f, a2 = 0.f, a3 = 0.f;

        #define STEP(j)                                                            \
        {                                                                          \
            int e  = eidx[j];                                                      \
            float v0 = p0[e], v1 = p1[e], v2 = p2[e], v3 = p3[e];                  \
            int fo = eflush[j];                                                    \
            float* oaddr = obase + (fo >> 1);                                      \
            asm volatile(                                                          \
                "{ .reg .pred p; setp.ne.s32 p, %0, 0;\n\t"                        \
                "@p red.global.add.v4.f32 [%1], {%2,%3,%4,%5}; }"                  \
                :: "r"(fo & 1), "l"(oaddr),                                        \
                   "f"(a0), "f"(a1), "f"(a2), "f"(a3) : "memory");                 \
            bool nb = (fo & 1);                                                    \
            a0 = nb ? v0 : a0 + v0;                                                \
            a1 = nb ? v1 : a1 + v1;                                                \
            a2 = nb ? v2 : a2 + v2;                                                \
            a3 = nb ? v3 : a3 + v3;                                                \
        }

        STEP(0) STEP(1) STEP(2) STEP(3) STEP(4) STEP(5)
        if (has7) { STEP(6) }   // warp-uniform (warps 0,1 only)
        #undef STEP

        // final flush (every thread has >= 1 entry)
        asm volatile("red.global.add.v4.f32 [%0], {%1,%2,%3,%4};"
                     :: "l"(obase + last_off), "f"(a0), "f"(a1), "f"(a2), "f"(a3)
                     : "memory");

        __syncthreads();   // all gathers on buffer st complete before refill

        if (tid == 0 && g + NSTAGE < NGROUPS) {
            const int gn = g + NSTAGE;
            mbar_expect_tx(mb, GROUP_BYTES);
            #pragma unroll
            for (int c = 0; c < NC; ++c) {
                bulk_g2s(ring_s + (uint32_t)((st * NC + c) * STRIDE) * 4,
                         featbase + (size_t)(gn * NC + c) * plane,
                         PLANE_BYTES, mb);
            }
        }
    }
}

// ---------------- Kernel 3: finalize, vectorized (divide by count, add positional) ----------------
__global__ void finalize_kernel(
    float4* __restrict__ out4,                 // (B, S, C/4) sums -> final
    const float* __restrict__ centroid,        // (B, S, 2)
    const float4* __restrict__ posW4,          // (2, C/4)
    const float4* __restrict__ posb4)          // (C/4,)
{
    const int C4 = CC / 4;
    int idx = blockIdx.x * blockDim.x + threadIdx.x;
    if (idx >= BB * SS * C4) return;
    int c4 = idx % C4;
    int bs = idx / C4;
    float inv = 1.0f / fmaxf(g_counts[bs], 1.0f);
    float cx = centroid[bs * 2 + 0] * (1.0f / WW);
    float cy = centroid[bs * 2 + 1] * (1.0f / HH);
    float4 w0 = posW4[c4];
    float4 w1 = posW4[C4 + c4];
    float4 bb = posb4[c4];
    float4 s = out4[idx];
    s.x = s.x * inv + fmaf(cx, w0.x, fmaf(cy, w1.x, bb.x));
    s.y = s.y * inv + fmaf(cx, w0.y, fmaf(cy, w1.y, bb.y));
    s.z = s.z * inv + fmaf(cx, w0.z, fmaf(cy, w1.z, bb.z));
    s.w = s.w * inv + fmaf(cx, w0.w, fmaf(cy, w1.w, bb.w));
    out4[idx] = s;
}

extern "C" void kernel_launch(void* const* d_in, const int* in_sizes, int n_in,
                              void* d_out, int out_size)
{
    // inputs: 0=img(unused) 1=features 2=segments(int32) 3=centroid_coords 4=pos_W 5=pos_b 6=max_segments
    const float* feat     = (const float*)d_in[1];
    const int*   seg      = (const int*)d_in[2];
    const float* centroid = (const float*)d_in[3];
    const float* posW     = (const float*)d_in[4];
    const float* posb     = (const float*)d_in[5];
    float* out = (float*)d_out;

    (void)in_sizes; (void)n_in; (void)out_size;

    static bool attr_set = false;
    if (!attr_set) {
        cudaFuncSetAttribute(accum_kernel,
                             cudaFuncAttributeMaxDynamicSharedMemorySize, SMEM_BYTES);
        attr_set = true;
    }

    const int n4 = BB * SS * CC / 4;
    zero_kernel<<<(n4 + 255) / 256, 256>>>((float4*)out);

    dim3 grid(ROWCHUNKS, 1, BB);
    accum_kernel<<<grid, NTH, SMEM_BYTES>>>(feat, seg, out);

    finalize_kernel<<<(n4 + 255) / 256, 256>>>((float4*)out, centroid,
                                               (const float4*)posW, (const float4*)posb);
}

// round 12
// speedup vs baseline: 1.1054x; 1.0281x over previous
#include <cuda_runtime.h>
#include <cstdint>

// Problem constants (fixed-shape instance)
#define BB 16
#define CC 192
#define HH 224
#define WW 224
#define SS 196

#define ROWCHUNKS 16
#define ROWS_PER (HH / ROWCHUNKS)     // 14
#define PIX (ROWS_PER * WW)           // 3136
#define PLANE_BYTES (PIX * 4)         // 12544 (contiguous per channel per chunk)

#define NC 4                          // channels per group
#define NGROUPS (CC / NC)             // 48
#define NSTAGE 2                      // one stage per team
#define STRIDE PIX                    // 3136
#define GROUP_BYTES (NC * PLANE_BYTES) // 50176
#define NTH 512
#define TEAM 256                      // threads per team

// dyn smem layout (bytes):
//   ring      : NSTAGE*NC*STRIDE f32 = 100352
//   sorted_idx: PIX u16              = 6272
//   sorted_seg: PIX u8               = 3136
//   hist      : SS i32               = 784
//   mbars     : NSTAGE u64           = 16
// sort scratch (segtmp PIX i32 + scanbuf NTH i32) overlaid into ring.
#define RING_FLOATS (NSTAGE * NC * STRIDE)
#define SMEM_BYTES (RING_FLOATS * 4 + PIX * 2 + PIX + SS * 4 + 16)  // 110,560 -> 2 CTAs/SM

__device__ float g_counts[BB * SS];

__device__ __forceinline__ uint32_t smem_u32(const void* p) {
    uint32_t a;
    asm("{ .reg .u64 t; cvta.to.shared.u64 t, %1; cvt.u32.u64 %0, t; }" : "=r"(a) : "l"(p));
    return a;
}
__device__ __forceinline__ void mbar_init(uint32_t mbar, uint32_t cnt) {
    asm volatile("mbarrier.init.shared.b64 [%0], %1;" :: "r"(mbar), "r"(cnt) : "memory");
}
__device__ __forceinline__ void mbar_expect_tx(uint32_t mbar, uint32_t bytes) {
    asm volatile("mbarrier.arrive.expect_tx.shared.b64 _, [%0], %1;" :: "r"(mbar), "r"(bytes) : "memory");
}
__device__ __forceinline__ void mbar_wait(uint32_t mbar, uint32_t parity) {
    asm volatile(
        "{\n\t"
        ".reg .pred P;\n\t"
        "W_%=:\n\t"
        "mbarrier.try_wait.parity.acquire.cta.shared::cta.b64 P, [%0], %1, 0x989680;\n\t"
        "@P bra D_%=;\n\t"
        "bra W_%=;\n\t"
        "D_%=:\n\t"
        "}" :: "r"(mbar), "r"(parity) : "memory");
}
__device__ __forceinline__ void bulk_g2s(uint32_t dst, const void* src, uint32_t bytes, uint32_t mbar) {
    asm volatile("cp.async.bulk.shared::cta.global.mbarrier::complete_tx::bytes [%0], [%1], %2, [%3];"
                 :: "r"(dst), "l"(src), "r"(bytes), "r"(mbar) : "memory");
}
__device__ __forceinline__ void named_bar(int id) {
    asm volatile("bar.sync %0, %1;" :: "r"(id), "r"(TEAM) : "memory");
}

// ---------------- Kernel 1: zero sums (d_out) and counts, vectorized ----------------
__global__ void zero_kernel(float4* __restrict__ out4) {
    const int n4 = BB * SS * CC / 4;   // 150528
    int idx = blockIdx.x * blockDim.x + threadIdx.x;
    if (idx < n4) out4[idx] = make_float4(0.f, 0.f, 0.f, 0.f);
    if (idx < BB * SS) g_counts[idx] = 0.0f;
}

// ---------------- Kernel 2: sort once + two-team pipelined gather ----------------
// grid: (ROWCHUNKS, 1, BB) = 256 CTAs, block: 512, 2 CTAs/SM -> single wave
// Team 0 (tid 0..255): even groups on ring stage 0. Team 1 (tid 256..511): odd groups on stage 1.
__global__ __launch_bounds__(NTH, 2) void accum_kernel(
    const float* __restrict__ feat,   // (B, C, H, W) fp32
    const int* __restrict__ seg,      // (B, H, W) int32
    float* __restrict__ out)          // (B, S, C) fp32 (sums)
{
    extern __shared__ char smem_raw[];
    float* ring = (float*)smem_raw;                                   // NSTAGE*NC*STRIDE f32
    unsigned short* sorted_idx = (unsigned short*)(ring + RING_FLOATS); // PIX u16
    unsigned char*  sorted_seg = (unsigned char*)(sorted_idx + PIX);    // PIX u8
    int* hist = (int*)(sorted_seg + PIX);                             // SS
    unsigned long long* mbars = (unsigned long long*)(hist + SS);     // NSTAGE

    // sort scratch overlaid into ring (dead before TMA starts)
    int* segtmp  = (int*)ring;        // PIX ints
    int* scanbuf = segtmp + PIX;      // NTH ints

    const int tid = threadIdx.x;
    const int b   = blockIdx.z;
    const int h0  = blockIdx.x * ROWS_PER;

    const uint32_t mbar0 = smem_u32(mbars);

    if (tid == 0) {
        #pragma unroll
        for (int s = 0; s < NSTAGE; ++s) mbar_init(mbar0 + 8 * s, 1);
    }

    // ================= Phase 1: counting sort by segment id (whole block) =================
    for (int i = tid; i < SS; i += NTH) hist[i] = 0;
    __syncthreads();

    const int* segbase = seg + ((size_t)b * HH + h0) * WW;   // contiguous PIX ints
    for (int i = tid; i < PIX; i += NTH) {
        int s = segbase[i];
        s = min(max(s, 0), SS - 1);
        segtmp[i] = s;
        atomicAdd(&hist[s], 1);
    }
    __syncthreads();

    // counts (each CTA owns a unique (b, rowchunk))
    for (int i = tid; i < SS; i += NTH)
        atomicAdd(&g_counts[b * SS + i], (float)hist[i]);

    // block-wide exclusive scan of hist (SS <= NTH)
    int v = (tid < SS) ? hist[tid] : 0;
    scanbuf[tid] = v;
    __syncthreads();
    #pragma unroll
    for (int d = 1; d < NTH; d <<= 1) {
        int t = (tid >= d) ? scanbuf[tid - d] : 0;
        __syncthreads();
        scanbuf[tid] += t;
        __syncthreads();
    }
    if (tid < SS) hist[tid] = scanbuf[tid] - v;  // exclusive start offsets
    __syncthreads();

    // scatter
    for (int i = tid; i < PIX; i += NTH) {
        int s = segtmp[i];
        int pos = atomicAdd(&hist[s], 1);
        sorted_idx[pos] = (unsigned short)i;
        sorted_seg[pos] = (unsigned char)s;
    }
    __syncthreads();   // sort done; ring scratch dead -> safe for TMA

    // ================= Phase 2: two independent team pipelines =================
    const float* featbase = feat + ((size_t)b * CC * HH + h0) * WW;  // + c*HH*WW
    const size_t plane = (size_t)HH * WW;
    const uint32_t ring_s = smem_u32(ring);

    // prologue: fill stage 0 with group 0, stage 1 with group 1
    if (tid == 0) {
        #pragma unroll
        for (int s = 0; s < NSTAGE; ++s) {
            mbar_expect_tx(mbar0 + 8 * s, GROUP_BYTES);
            #pragma unroll
            for (int c = 0; c < NC; ++c) {
                bulk_g2s(ring_s + (uint32_t)((s * NC + c) * STRIDE) * 4,
                         featbase + (size_t)(s * NC + c) * plane,
                         PLANE_BYTES, mbar0 + 8 * s);
            }
        }
    }

    const int team = tid >> 8;          // 0 or 1
    const int ttid = tid & (TEAM - 1);  // 0..255
    const int barid = team + 1;         // named barrier 1 or 2

    // per-team entry partition: PIX/TEAM = 12.25 -> 64 threads x13 + 192 x12
    const bool has13 = (ttid < 64);
    const int base   = has13 ? ttid * 13 : ttid * 12 + 64;

    // register-cached window: eidx[j] = pixel idx, eflush[j] = (prev_s*CC)<<1 | boundary
    int eidx[13];
    int eflush[13];
    int last_off;
    {
        int prev_s = -1;
        #pragma unroll
        for (int j = 0; j < 13; ++j) {
            int jj = base + ((j == 12 && !has13) ? 11 : j);  // replicate (unused) for 12-entry threads
            int ij = sorted_idx[jj];
            int sj = sorted_seg[jj];
            eidx[j] = ij;
            int nb = (j > 0 && sj != prev_s) ? 1 : 0;
            eflush[j] = ((prev_s < 0 ? 0 : prev_s * CC) << 1) | nb;
            prev_s = sj;
        }
        last_off = prev_s * CC;
    }

    const int st = team;                       // this team's ring stage
    const uint32_t mb = mbar0 + 8 * st;
    const float* p0 = ring + (st * NC + 0) * STRIDE;
    const float* p1 = ring + (st * NC + 1) * STRIDE;
    const float* p2 = ring + (st * NC + 2) * STRIDE;
    const float* p3 = ring + (st * NC + 3) * STRIDE;

    float* obase0 = out + (size_t)b * SS * CC;

    // team loop: 24 groups each (team 0: 0,2,..,46 ; team 1: 1,3,..,47)
    for (int u = 0; u < NGROUPS / 2; ++u) {
        const int g = 2 * u + team;
        mbar_wait(mb, u & 1);   // u-th use of this stage's full barrier

        float* obase = obase0 + g * NC;

        float a0 = 0.f, a1 = 0.f, a2 = 0.f, a3 = 0.f;

        #define STEP(j)                                                            \
        {                                                                          \
            int e  = eidx[j];                                                      \
            float v0 = p0[e], v1 = p1[e], v2 = p2[e], v3 = p3[e];                  \
            int fo = eflush[j];                                                    \
            float* oaddr = obase + (fo >> 1);                                      \
            asm volatile(                                                          \
                "{ .reg .pred p; setp.ne.s32 p, %0, 0;\n\t"                        \
                "@p red.global.add.v4.f32 [%1], {%2,%3,%4,%5}; }"                  \
                :: "r"(fo & 1), "l"(oaddr),                                        \
                   "f"(a0), "f"(a1), "f"(a2), "f"(a3) : "memory");                 \
            bool nb = (fo & 1);                                                    \
            a0 = nb ? v0 : a0 + v0;                                                \
            a1 = nb ? v1 : a1 + v1;                                                \
            a2 = nb ? v2 : a2 + v2;                                                \
            a3 = nb ? v3 : a3 + v3;                                                \
        }

        STEP(0) STEP(1) STEP(2) STEP(3) STEP(4) STEP(5)
        STEP(6) STEP(7) STEP(8) STEP(9) STEP(10) STEP(11)
        if (has13) { STEP(12) }   // warp-uniform (team warps 0,1 only)
        #undef STEP

        // final flush (every thread has >= 1 entry)
        asm volatile("red.global.add.v4.f32 [%0], {%1,%2,%3,%4};"
                     :: "l"(obase + last_off), "f"(a0), "f"(a1), "f"(a2), "f"(a3)
                     : "memory");

        named_bar(barid);   // this team done reading stage st

        // team leader refills own stage with group g+2
        if (ttid == 0 && g + 2 < NGROUPS) {
            const int gn = g + 2;
            mbar_expect_tx(mb, GROUP_BYTES);
            #pragma unroll
            for (int c = 0; c < NC; ++c) {
                bulk_g2s(ring_s + (uint32_t)((st * NC + c) * STRIDE) * 4,
                         featbase + (size_t)(gn * NC + c) * plane,
                         PLANE_BYTES, mb);
            }
        }
    }
}

// ---------------- Kernel 3: finalize, vectorized (divide by count, add positional) ----------------
__global__ void finalize_kernel(
    float4* __restrict__ out4,                 // (B, S, C/4) sums -> final
    const float* __restrict__ centroid,        // (B, S, 2)
    const float4* __restrict__ posW4,          // (2, C/4)
    const float4* __restrict__ posb4)          // (C/4,)
{
    const int C4 = CC / 4;
    int idx = blockIdx.x * blockDim.x + threadIdx.x;
    if (idx >= BB * SS * C4) return;
    int c4 = idx % C4;
    int bs = idx / C4;
    float inv = 1.0f / fmaxf(g_counts[bs], 1.0f);
    float cx = centroid[bs * 2 + 0] * (1.0f / WW);
    float cy = centroid[bs * 2 + 1] * (1.0f / HH);
    float4 w0 = posW4[c4];
    float4 w1 = posW4[C4 + c4];
    float4 bb = posb4[c4];
    float4 s = out4[idx];
    s.x = s.x * inv + fmaf(cx, w0.x, fmaf(cy, w1.x, bb.x));
    s.y = s.y * inv + fmaf(cx, w0.y, fmaf(cy, w1.y, bb.y));
    s.z = s.z * inv + fmaf(cx, w0.z, fmaf(cy, w1.z, bb.z));
    s.w = s.w * inv + fmaf(cx, w0.w, fmaf(cy, w1.w, bb.w));
    out4[idx] = s;
}

extern "C" void kernel_launch(void* const* d_in, const int* in_sizes, int n_in,
                              void* d_out, int out_size)
{
    // inputs: 0=img(unused) 1=features 2=segments(int32) 3=centroid_coords 4=pos_W 5=pos_b 6=max_segments
    const float* feat     = (const float*)d_in[1];
    const int*   seg      = (const int*)d_in[2];
    const float* centroid = (const float*)d_in[3];
    const float* posW     = (const float*)d_in[4];
    const float* posb     = (const float*)d_in[5];
    float* out = (float*)d_out;

    (void)in_sizes; (void)n_in; (void)out_size;

    static bool attr_set = false;
    if (!attr_set) {
        cudaFuncSetAttribute(accum_kernel,
                             cudaFuncAttributeMaxDynamicSharedMemorySize, SMEM_BYTES);
        attr_set = true;
    }

    const int n4 = BB * SS * CC / 4;
    zero_kernel<<<(n4 + 255) / 256, 256>>>((float4*)out);

    dim3 grid(ROWCHUNKS, 1, BB);
    accum_kernel<<<grid, NTH, SMEM_BYTES>>>(feat, seg, out);

    finalize_kernel<<<(n4 + 255) / 256, 256>>>((float4*)out, centroid,
                                               (const float4*)posW, (const float4*)posb);
}

// round 13
// speedup vs baseline: 1.1512x; 1.0415x over previous
#include <cuda_runtime.h>
#include <cstdint>

// Problem constants (fixed-shape instance)
#define BB 16
#define CC 192
#define HH 224
#define WW 224
#define SS 196

#define ROWCHUNKS 16
#define ROWS_PER (HH / ROWCHUNKS)     // 14
#define PIX (ROWS_PER * WW)           // 3136
#define PLANE_BYTES (PIX * 4)         // 12544 (contiguous per channel per chunk)

#define NC 4                          // channels per group
#define NGROUPS (CC / NC)             // 48
#define NSTAGE 2                      // one stage per team
#define STRIDE PIX                    // 3136
#define GROUP_BYTES (NC * PLANE_BYTES) // 50176
#define NTH 512
#define TEAM 256                      // threads per team

// dyn smem layout (bytes):
//   ring      : NSTAGE*NC*STRIDE f32 = 100352
//   sorted_idx: PIX u16              = 6272
//   sorted_seg: PIX u8               = 3136
//   hist      : SS i32               = 784
//   mbars     : NSTAGE u64           = 16
// sort scratch (segtmp PIX i32 + scanbuf NTH i32) overlaid into ring.
#define RING_FLOATS (NSTAGE * NC * STRIDE)
#define SMEM_BYTES (RING_FLOATS * 4 + PIX * 2 + PIX + SS * 4 + 16)  // 110,560 -> 2 CTAs/SM

__device__ float g_counts[BB * SS];

__device__ __forceinline__ uint32_t smem_u32(const void* p) {
    uint32_t a;
    asm("{ .reg .u64 t; cvta.to.shared.u64 t, %1; cvt.u32.u64 %0, t; }" : "=r"(a) : "l"(p));
    return a;
}
__device__ __forceinline__ void mbar_init(uint32_t mbar, uint32_t cnt) {
    asm volatile("mbarrier.init.shared.b64 [%0], %1;" :: "r"(mbar), "r"(cnt) : "memory");
}
__device__ __forceinline__ void mbar_expect_tx(uint32_t mbar, uint32_t bytes) {
    asm volatile("mbarrier.arrive.expect_tx.shared.b64 _, [%0], %1;" :: "r"(mbar), "r"(bytes) : "memory");
}
__device__ __forceinline__ void mbar_wait(uint32_t mbar, uint32_t parity) {
    asm volatile(
        "{\n\t"
        ".reg .pred P;\n\t"
        "W_%=:\n\t"
        "mbarrier.try_wait.parity.acquire.cta.shared::cta.b64 P, [%0], %1, 0x989680;\n\t"
        "@P bra D_%=;\n\t"
        "bra W_%=;\n\t"
        "D_%=:\n\t"
        "}" :: "r"(mbar), "r"(parity) : "memory");
}
__device__ __forceinline__ void bulk_g2s(uint32_t dst, const void* src, uint32_t bytes, uint32_t mbar) {
    asm volatile("cp.async.bulk.shared::cta.global.mbarrier::complete_tx::bytes [%0], [%1], %2, [%3];"
                 :: "r"(dst), "l"(src), "r"(bytes), "r"(mbar) : "memory");
}
__device__ __forceinline__ void named_bar(int id) {
    asm volatile("bar.sync %0, %1;" :: "r"(id), "r"(TEAM) : "memory");
}

// ---------------- Kernel 2: sort once + two-team pipelined gather ----------------
// grid: (ROWCHUNKS, 1, BB) = 256 CTAs, block: 512, 2 CTAs/SM -> single wave
// Team 0 (tid 0..255): even groups on ring stage 0. Team 1 (tid 256..511): odd groups on stage 1.
__global__ __launch_bounds__(NTH, 2) void accum_kernel(
    const float* __restrict__ feat,   // (B, C, H, W) fp32
    const int* __restrict__ seg,      // (B, H, W) int32
    float* __restrict__ out)          // (B, S, C) fp32 (sums)
{
    extern __shared__ char smem_raw[];
    float* ring = (float*)smem_raw;                                   // NSTAGE*NC*STRIDE f32
    unsigned short* sorted_idx = (unsigned short*)(ring + RING_FLOATS); // PIX u16
    unsigned char*  sorted_seg = (unsigned char*)(sorted_idx + PIX);    // PIX u8
    int* hist = (int*)(sorted_seg + PIX);                             // SS
    unsigned long long* mbars = (unsigned long long*)(hist + SS);     // NSTAGE

    // sort scratch overlaid into ring (dead before TMA starts)
    int* segtmp  = (int*)ring;        // PIX ints
    int* scanbuf = segtmp + PIX;      // NTH ints

    const int tid = threadIdx.x;
    const int b   = blockIdx.z;
    const int h0  = blockIdx.x * ROWS_PER;

    const uint32_t mbar0 = smem_u32(mbars);

    if (tid == 0) {
        #pragma unroll
        for (int s = 0; s < NSTAGE; ++s) mbar_init(mbar0 + 8 * s, 1);
    }

    // ================= Phase 1: counting sort by segment id (whole block) =================
    for (int i = tid; i < SS; i += NTH) hist[i] = 0;
    __syncthreads();

    const int* segbase = seg + ((size_t)b * HH + h0) * WW;   // contiguous PIX ints
    for (int i = tid; i < PIX; i += NTH) {
        int s = segbase[i];
        s = min(max(s, 0), SS - 1);
        segtmp[i] = s;
        atomicAdd(&hist[s], 1);
    }
    __syncthreads();

    // counts (each CTA owns a unique (b, rowchunk))
    for (int i = tid; i < SS; i += NTH)
        atomicAdd(&g_counts[b * SS + i], (float)hist[i]);

    // block-wide exclusive scan of hist (SS <= NTH)
    int v = (tid < SS) ? hist[tid] : 0;
    scanbuf[tid] = v;
    __syncthreads();
    #pragma unroll
    for (int d = 1; d < NTH; d <<= 1) {
        int t = (tid >= d) ? scanbuf[tid - d] : 0;
        __syncthreads();
        scanbuf[tid] += t;
        __syncthreads();
    }
    if (tid < SS) hist[tid] = scanbuf[tid] - v;  // exclusive start offsets
    __syncthreads();

    // scatter
    for (int i = tid; i < PIX; i += NTH) {
        int s = segtmp[i];
        int pos = atomicAdd(&hist[s], 1);
        sorted_idx[pos] = (unsigned short)i;
        sorted_seg[pos] = (unsigned char)s;
    }
    __syncthreads();   // sort done; ring scratch dead -> safe for TMA

    // ================= Phase 2: two independent team pipelines =================
    const float* featbase = feat + ((size_t)b * CC * HH + h0) * WW;  // + c*HH*WW
    const size_t plane = (size_t)HH * WW;
    const uint32_t ring_s = smem_u32(ring);

    // prologue: fill stage 0 with group 0, stage 1 with group 1
    if (tid == 0) {
        #pragma unroll
        for (int s = 0; s < NSTAGE; ++s) {
            mbar_expect_tx(mbar0 + 8 * s, GROUP_BYTES);
            #pragma unroll
            for (int c = 0; c < NC; ++c) {
                bulk_g2s(ring_s + (uint32_t)((s * NC + c) * STRIDE) * 4,
                         featbase + (size_t)(s * NC + c) * plane,
                         PLANE_BYTES, mbar0 + 8 * s);
            }
        }
    }

    const int team = tid >> 8;          // 0 or 1
    const int ttid = tid & (TEAM - 1);  // 0..255
    const int barid = team + 1;         // named barrier 1 or 2

    // per-team entry partition: PIX/TEAM = 12.25 -> 64 threads x13 + 192 x12
    const bool has13 = (ttid < 64);
    const int base   = has13 ? ttid * 13 : ttid * 12 + 64;

    // register-cached window: eidx[j] = pixel idx, eflush[j] = (prev_s*CC)<<1 | boundary
    int eidx[13];
    int eflush[13];
    int last_off;
    {
        int prev_s = -1;
        #pragma unroll
        for (int j = 0; j < 13; ++j) {
            int jj = base + ((j == 12 && !has13) ? 11 : j);  // replicate (unused) for 12-entry threads
            int ij = sorted_idx[jj];
            int sj = sorted_seg[jj];
            eidx[j] = ij;
            int nb = (j > 0 && sj != prev_s) ? 1 : 0;
            eflush[j] = ((prev_s < 0 ? 0 : prev_s * CC) << 1) | nb;
            prev_s = sj;
        }
        last_off = prev_s * CC;
    }

    const int st = team;                       // this team's ring stage
    const uint32_t mb = mbar0 + 8 * st;
    const float* p0 = ring + (st * NC + 0) * STRIDE;
    const float* p1 = ring + (st * NC + 1) * STRIDE;
    const float* p2 = ring + (st * NC + 2) * STRIDE;
    const float* p3 = ring + (st * NC + 3) * STRIDE;

    float* obase0 = out + (size_t)b * SS * CC;

    // team loop: 24 groups each (team 0: 0,2,..,46 ; team 1: 1,3,..,47)
    for (int u = 0; u < NGROUPS / 2; ++u) {
        const int g = 2 * u + team;
        mbar_wait(mb, u & 1);   // u-th use of this stage's full barrier

        float* obase = obase0 + g * NC;

        float a0 = 0.f, a1 = 0.f, a2 = 0.f, a3 = 0.f;

        // select-free accumulate: k = 1.0f (continue run) or 0.0f (boundary), a = fma(a,k,v)
        #define STEP(j)                                                            \
        {                                                                          \
            int e  = eidx[j];                                                      \
            float v0 = p0[e], v1 = p1[e], v2 = p2[e], v3 = p3[e];                  \
            int fo = eflush[j];                                                    \
            float* oaddr = obase + (fo >> 1);                                      \
            asm volatile(                                                          \
                "{ .reg .pred p; setp.ne.s32 p, %0, 0;\n\t"                        \
                "@p red.global.add.v4.f32 [%1], {%2,%3,%4,%5}; }"                  \
                :: "r"(fo & 1), "l"(oaddr),                                        \
                   "f"(a0), "f"(a1), "f"(a2), "f"(a3) : "memory");                 \
            float k = __uint_as_float(0x3F800000u & (uint32_t)((fo & 1) - 1));     \
            a0 = fmaf(a0, k, v0);                                                  \
            a1 = fmaf(a1, k, v1);                                                  \
            a2 = fmaf(a2, k, v2);                                                  \
            a3 = fmaf(a3, k, v3);                                                  \
        }

        STEP(0) STEP(1) STEP(2) STEP(3) STEP(4) STEP(5)
        STEP(6) STEP(7) STEP(8) STEP(9) STEP(10) STEP(11)
        if (has13) { STEP(12) }   // warp-uniform (team warps 0,1 only)
        #undef STEP

        // final flush (every thread has >= 1 entry)
        asm volatile("red.global.add.v4.f32 [%0], {%1,%2,%3,%4};"
                     :: "l"(obase + last_off), "f"(a0), "f"(a1), "f"(a2), "f"(a3)
                     : "memory");

        named_bar(barid);   // this team done reading stage st

        // team leader refills own stage with group g+2
        if (ttid == 0 && g + 2 < NGROUPS) {
            const int gn = g + 2;
            mbar_expect_tx(mb, GROUP_BYTES);
            #pragma unroll
            for (int c = 0; c < NC; ++c) {
                bulk_g2s(ring_s + (uint32_t)((st * NC + c) * STRIDE) * 4,
                         featbase + (size_t)(gn * NC + c) * plane,
                         PLANE_BYTES, mb);
            }
        }
    }
}

// ---------------- Kernel 3: finalize, vectorized (divide by count, add positional) ----------------
__global__ void finalize_kernel(
    float4* __restrict__ out4,                 // (B, S, C/4) sums -> final
    const float* __restrict__ centroid,        // (B, S, 2)
    const float4* __restrict__ posW4,          // (2, C/4)
    const float4* __restrict__ posb4)          // (C/4,)
{
    const int C4 = CC / 4;
    int idx = blockIdx.x * blockDim.x + threadIdx.x;
    if (idx >= BB * SS * C4) return;
    int c4 = idx % C4;
    int bs = idx / C4;
    float inv = 1.0f / fmaxf(g_counts[bs], 1.0f);
    float cx = centroid[bs * 2 + 0] * (1.0f / WW);
    float cy = centroid[bs * 2 + 1] * (1.0f / HH);
    float4 w0 = posW4[c4];
    float4 w1 = posW4[C4 + c4];
    float4 bb = posb4[c4];
    float4 s = out4[idx];
    s.x = s.x * inv + fmaf(cx, w0.x, fmaf(cy, w1.x, bb.x));
    s.y = s.y * inv + fmaf(cx, w0.y, fmaf(cy, w1.y, bb.y));
    s.z = s.z * inv + fmaf(cx, w0.z, fmaf(cy, w1.z, bb.z));
    s.w = s.w * inv + fmaf(cx, w0.w, fmaf(cy, w1.w, bb.w));
    out4[idx] = s;
}

extern "C" void kernel_launch(void* const* d_in, const int* in_sizes, int n_in,
                              void* d_out, int out_size)
{
    // inputs: 0=img(unused) 1=features 2=segments(int32) 3=centroid_coords 4=pos_W 5=pos_b 6=max_segments
    const float* feat     = (const float*)d_in[1];
    const int*   seg      = (const int*)d_in[2];
    const float* centroid = (const float*)d_in[3];
    const float* posW     = (const float*)d_in[4];
    const float* posb     = (const float*)d_in[5];
    float* out = (float*)d_out;

    (void)in_sizes; (void)n_in; (void)out_size;

    static bool init_done = false;
    static void* gcounts_ptr = nullptr;
    if (!init_done) {
        cudaFuncSetAttribute(accum_kernel,
                             cudaFuncAttributeMaxDynamicSharedMemorySize, SMEM_BYTES);
        cudaGetSymbolAddress(&gcounts_ptr, g_counts);
        init_done = true;
    }

    // zero via memset nodes (cheaper than a kernel; graph-capturable)
    cudaMemsetAsync(out, 0, (size_t)BB * SS * CC * sizeof(float), 0);
    cudaMemsetAsync(gcounts_ptr, 0, (size_t)BB * SS * sizeof(float), 0);

    dim3 grid(ROWCHUNKS, 1, BB);
    accum_kernel<<<grid, NTH, SMEM_BYTES>>>(feat, seg, out);

    const int n4 = BB * SS * CC / 4;
    finalize_kernel<<<(n4 + 255) / 256, 256>>>((float4*)out, centroid,
                                               (const float4*)posW, (const float4*)posb);
}

// round 14
// speedup vs baseline: 1.1704x; 1.0166x over previous
#include <cuda_runtime.h>
#include <cstdint>

// Problem constants (fixed-shape instance)
#define BB 16
#define CC 192
#define HH 224
#define WW 224
#define SS 196

#define NCTA 296                      // = 148 SMs * 2 CTAs -> exact single wave
#define PIXMAX (13 * WW)              // 2912 (max rows per chunk = 13)

#define NC 4                          // channels per group
#define NGROUPS (CC / NC)             // 48
#define NSTAGE 2                      // one stage per team
#define STRIDE PIXMAX                 // ring plane stride (floats)
#define NTH 512
#define TEAM 256                      // threads per team

// dyn smem layout (bytes):
//   ring      : NSTAGE*NC*STRIDE f32 = 93184
//   sorted_idx: PIXMAX u16           = 5824
//   sorted_seg: PIXMAX u8            = 2912
//   hist      : SS i32               = 784
//   mbars     : NSTAGE u64           = 16
// sort scratch (segtmp PIXMAX i32 + scanbuf NTH i32) overlaid into ring.
#define RING_FLOATS (NSTAGE * NC * STRIDE)
#define SMEM_BYTES (RING_FLOATS * 4 + PIXMAX * 2 + PIXMAX + SS * 4 + 16)  // 102,720 -> 2 CTAs/SM

__device__ float g_counts[BB * SS];

__device__ __forceinline__ uint32_t smem_u32(const void* p) {
    uint32_t a;
    asm("{ .reg .u64 t; cvta.to.shared.u64 t, %1; cvt.u32.u64 %0, t; }" : "=r"(a) : "l"(p));
    return a;
}
__device__ __forceinline__ void mbar_init(uint32_t mbar, uint32_t cnt) {
    asm volatile("mbarrier.init.shared.b64 [%0], %1;" :: "r"(mbar), "r"(cnt) : "memory");
}
__device__ __forceinline__ void mbar_expect_tx(uint32_t mbar, uint32_t bytes) {
    asm volatile("mbarrier.arrive.expect_tx.shared.b64 _, [%0], %1;" :: "r"(mbar), "r"(bytes) : "memory");
}
__device__ __forceinline__ void mbar_wait(uint32_t mbar, uint32_t parity) {
    asm volatile(
        "{\n\t"
        ".reg .pred P;\n\t"
        "W_%=:\n\t"
        "mbarrier.try_wait.parity.acquire.cta.shared::cta.b64 P, [%0], %1, 0x989680;\n\t"
        "@P bra D_%=;\n\t"
        "bra W_%=;\n\t"
        "D_%=:\n\t"
        "}" :: "r"(mbar), "r"(parity) : "memory");
}
__device__ __forceinline__ void bulk_g2s(uint32_t dst, const void* src, uint32_t bytes, uint32_t mbar) {
    asm volatile("cp.async.bulk.shared::cta.global.mbarrier::complete_tx::bytes [%0], [%1], %2, [%3];"
                 :: "r"(dst), "l"(src), "r"(bytes), "r"(mbar) : "memory");
}
__device__ __forceinline__ void named_bar(int id) {
    asm volatile("bar.sync %0, %1;" :: "r"(id), "r"(TEAM) : "memory");
}

// ---------------- Kernel 2: sort once + two-team pipelined gather (exact-fill grid) ----------------
// grid: 296 CTAs (1D), block: 512, 2 CTAs/SM -> perfectly filled single wave
__global__ __launch_bounds__(NTH, 2) void accum_kernel(
    const float* __restrict__ feat,   // (B, C, H, W) fp32
    const int* __restrict__ seg,      // (B, H, W) int32
    float* __restrict__ out)          // (B, S, C) fp32 (sums)
{
    extern __shared__ char smem_raw[];
    float* ring = (float*)smem_raw;                                     // NSTAGE*NC*STRIDE f32
    unsigned short* sorted_idx = (unsigned short*)(ring + RING_FLOATS); // PIXMAX u16
    unsigned char*  sorted_seg = (unsigned char*)(sorted_idx + PIXMAX); // PIXMAX u8
    int* hist = (int*)(sorted_seg + PIXMAX);                            // SS
    unsigned long long* mbars = (unsigned long long*)(hist + SS);       // NSTAGE

    // sort scratch overlaid into ring (dead before TMA starts)
    int* segtmp  = (int*)ring;        // PIXMAX ints
    int* scanbuf = segtmp + PIXMAX;   // NTH ints

    const int tid = threadIdx.x;
    const int bid = blockIdx.x;

    // ---- chunk decomposition: images 0..7 -> 18 chunks (rows 13x8 + 12x10),
    //                           images 8..15 -> 19 chunks (rows 12x15 + 11x4). 8*18+8*19 = 296.
    int b, h0, nrows;
    if (bid < 144) {
        b = bid / 18;
        int cid = bid - b * 18;
        nrows = 12 + (cid < 8 ? 1 : 0);
        h0 = cid * 12 + min(cid, 8);
    } else {
        int r = bid - 144;
        b = 8 + r / 19;
        int cid = r - (b - 8) * 19;
        nrows = 11 + (cid < 15 ? 1 : 0);
        h0 = cid * 11 + min(cid, 15);
    }
    const int pix = nrows * WW;                    // 2464 / 2688 / 2912
    const uint32_t plane_bytes = (uint32_t)pix * 4;
    const uint32_t group_bytes = (uint32_t)NC * plane_bytes;

    const uint32_t mbar0 = smem_u32(mbars);

    if (tid == 0) {
        #pragma unroll
        for (int s = 0; s < NSTAGE; ++s) mbar_init(mbar0 + 8 * s, 1);
    }

    // ================= Phase 1: counting sort by segment id (whole block) =================
    for (int i = tid; i < SS; i += NTH) hist[i] = 0;
    __syncthreads();

    const int* segbase = seg + ((size_t)b * HH + h0) * WW;   // contiguous pix ints
    for (int i = tid; i < pix; i += NTH) {
        int s = segbase[i];
        s = min(max(s, 0), SS - 1);
        segtmp[i] = s;
        atomicAdd(&hist[s], 1);
    }
    __syncthreads();

    // counts (each CTA owns a unique (b, rowchunk))
    for (int i = tid; i < SS; i += NTH)
        atomicAdd(&g_counts[b * SS + i], (float)hist[i]);

    // block-wide exclusive scan of hist (SS <= NTH)
    int v = (tid < SS) ? hist[tid] : 0;
    scanbuf[tid] = v;
    __syncthreads();
    #pragma unroll
    for (int d = 1; d < NTH; d <<= 1) {
        int t = (tid >= d) ? scanbuf[tid - d] : 0;
        __syncthreads();
        scanbuf[tid] += t;
        __syncthreads();
    }
    if (tid < SS) hist[tid] = scanbuf[tid] - v;  // exclusive start offsets
    __syncthreads();

    // scatter
    for (int i = tid; i < pix; i += NTH) {
        int s = segtmp[i];
        int pos = atomicAdd(&hist[s], 1);
        sorted_idx[pos] = (unsigned short)i;
        sorted_seg[pos] = (unsigned char)s;
    }
    __syncthreads();   // sort done; ring scratch dead -> safe for TMA

    // ================= Phase 2: two independent team pipelines =================
    const float* featbase = feat + ((size_t)b * CC * HH + h0) * WW;  // + c*HH*WW
    const size_t plane = (size_t)HH * WW;
    const uint32_t ring_s = smem_u32(ring);

    // prologue: fill stage 0 with group 0, stage 1 with group 1
    if (tid == 0) {
        #pragma unroll
        for (int s = 0; s < NSTAGE; ++s) {
            mbar_expect_tx(mbar0 + 8 * s, group_bytes);
            #pragma unroll
            for (int c = 0; c < NC; ++c) {
                bulk_g2s(ring_s + (uint32_t)((s * NC + c) * STRIDE) * 4,
                         featbase + (size_t)(s * NC + c) * plane,
                         plane_bytes, mbar0 + 8 * s);
            }
        }
    }

    const int team = tid >> 8;          // 0 or 1
    const int ttid = tid & (TEAM - 1);  // 0..255
    const int barid = team + 1;         // named barrier 1 or 2

    // balanced per-thread windows over [0, pix): size 9..12
    const int wst = (ttid * pix) >> 8;
    const int wen = ((ttid + 1) * pix) >> 8;
    const int nw  = wen - wst;          // >= 9 (pix >= 2464)

    // register-cached window: eidx[j] = pixel idx,
    // eflush[j] = (prev_off << 2) | (valid << 1) | boundary
    int eidx[12];
    int eflush[12];
    int last_off;
    {
        int prev_s = -1;
        #pragma unroll
        for (int j = 0; j < 12; ++j) {
            int valid = (j < nw) ? 1 : 0;
            int jj = wst + (valid ? j : (nw - 1));   // replicate last valid entry
            int ij = sorted_idx[jj];
            int sj = sorted_seg[jj];
            eidx[j] = ij;
            int nb = (valid && j > 0 && sj != prev_s) ? 1 : 0;
            eflush[j] = ((prev_s < 0 ? 0 : prev_s * CC) << 2) | (valid << 1) | nb;
            if (valid) prev_s = sj;
        }
        last_off = prev_s * CC;
    }

    const int st = team;                       // this team's ring stage
    const uint32_t mb = mbar0 + 8 * st;
    const float* p0 = ring + (st * NC + 0) * STRIDE;
    const float* p1 = ring + (st * NC + 1) * STRIDE;
    const float* p2 = ring + (st * NC + 2) * STRIDE;
    const float* p3 = ring + (st * NC + 3) * STRIDE;

    float* obase0 = out + (size_t)b * SS * CC;

    // team loop: 24 groups each (team 0: 0,2,..,46 ; team 1: 1,3,..,47)
    for (int u = 0; u < NGROUPS / 2; ++u) {
        const int g = 2 * u + team;
        mbar_wait(mb, u & 1);   // u-th use of this stage's full barrier

        float* obase = obase0 + g * NC;

        float a0 = 0.f, a1 = 0.f, a2 = 0.f, a3 = 0.f;

        // entries 0..8 always valid (nw >= 9): no valid-scale needed
        #define STEP(j)                                                            \
        {                                                                          \
            int e  = eidx[j];                                                      \
            float v0 = p0[e], v1 = p1[e], v2 = p2[e], v3 = p3[e];                  \
            int fo = eflush[j];                                                    \
            float* oaddr = obase + (fo >> 2);                                      \
            asm volatile(                                                          \
                "{ .reg .pred p; setp.ne.s32 p, %0, 0;\n\t"                        \
                "@p red.global.add.v4.f32 [%1], {%2,%3,%4,%5}; }"                  \
                :: "r"(fo & 1), "l"(oaddr),                                        \
                   "f"(a0), "f"(a1), "f"(a2), "f"(a3) : "memory");                 \
            float k = __uint_as_float(0x3F800000u & (uint32_t)((fo & 1) - 1));     \
            a0 = fmaf(a0, k, v0);                                                  \
            a1 = fmaf(a1, k, v1);                                                  \
            a2 = fmaf(a2, k, v2);                                                  \
            a3 = fmaf(a3, k, v3);                                                  \
        }

        // entries 9..11: may be padding -> zero their contribution via valid mask
        #define STEPV(j)                                                           \
        {                                                                          \
            int e  = eidx[j];                                                      \
            float v0 = p0[e], v1 = p1[e], v2 = p2[e], v3 = p3[e];                  \
            int fo = eflush[j];                                                    \
            float* oaddr = obase + (fo >> 2);                                      \
            asm volatile(                                                          \
                "{ .reg .pred p; setp.ne.s32 p, %0, 0;\n\t"                        \
                "@p red.global.add.v4.f32 [%1], {%2,%3,%4,%5}; }"                  \
                :: "r"(fo & 1), "l"(oaddr),                                        \
                   "f"(a0), "f"(a1), "f"(a2), "f"(a3) : "memory");                 \
            float k  = __uint_as_float(0x3F800000u & (uint32_t)((fo & 1) - 1));    \
            float vs = __uint_as_float(0x3F800000u & (uint32_t)(0 - ((fo >> 1) & 1))); \
            a0 = fmaf(a0, k, v0 * vs);                                             \
            a1 = fmaf(a1, k, v1 * vs);                                             \
            a2 = fmaf(a2, k, v2 * vs);                                             \
            a3 = fmaf(a3, k, v3 * vs);                                             \
        }

        STEP(0) STEP(1) STEP(2) STEP(3) STEP(4) STEP(5)
        STEP(6) STEP(7) STEP(8)
        STEPV(9) STEPV(10) STEPV(11)
        #undef STEP
        #undef STEPV

        // final flush (every thread has >= 9 entries)
        asm volatile("red.global.add.v4.f32 [%0], {%1,%2,%3,%4};"
                     :: "l"(obase + last_off), "f"(a0), "f"(a1), "f"(a2), "f"(a3)
                     : "memory");

        named_bar(barid);   // this team done reading stage st

        // team leader refills own stage with group g+2
        if (ttid == 0 && g + 2 < NGROUPS) {
            const int gn = g + 2;
            mbar_expect_tx(mb, group_bytes);
            #pragma unroll
            for (int c = 0; c < NC; ++c) {
                bulk_g2s(ring_s + (uint32_t)((st * NC + c) * STRIDE) * 4,
                         featbase + (size_t)(gn * NC + c) * plane,
                         plane_bytes, mb);
            }
        }
    }
}

// ---------------- Kernel 3: finalize, vectorized (divide by count, add positional) ----------------
__global__ void finalize_kernel(
    float4* __restrict__ out4,                 // (B, S, C/4) sums -> final
    const float* __restrict__ centroid,        // (B, S, 2)
    const float4* __restrict__ posW4,          // (2, C/4)
    const float4* __restrict__ posb4)          // (C/4,)
{
    const int C4 = CC / 4;
    int idx = blockIdx.x * blockDim.x + threadIdx.x;
    if (idx >= BB * SS * C4) return;
    int c4 = idx % C4;
    int bs = idx / C4;
    float inv = 1.0f / fmaxf(g_counts[bs], 1.0f);
    float cx = centroid[bs * 2 + 0] * (1.0f / WW);
    float cy = centroid[bs * 2 + 1] * (1.0f / HH);
    float4 w0 = posW4[c4];
    float4 w1 = posW4[C4 + c4];
    float4 bb = posb4[c4];
    float4 s = out4[idx];
    s.x = s.x * inv + fmaf(cx, w0.x, fmaf(cy, w1.x, bb.x));
    s.y = s.y * inv + fmaf(cx, w0.y, fmaf(cy, w1.y, bb.y));
    s.z = s.z * inv + fmaf(cx, w0.z, fmaf(cy, w1.z, bb.z));
    s.w = s.w * inv + fmaf(cx, w0.w, fmaf(cy, w1.w, bb.w));
    out4[idx] = s;
}

extern "C" void kernel_launch(void* const* d_in, const int* in_sizes, int n_in,
                              void* d_out, int out_size)
{
    // inputs: 0=img(unused) 1=features 2=segments(int32) 3=centroid_coords 4=pos_W 5=pos_b 6=max_segments
    const float* feat     = (const float*)d_in[1];
    const int*   seg      = (const int*)d_in[2];
    const float* centroid = (const float*)d_in[3];
    const float* posW     = (const float*)d_in[4];
    const float* posb     = (const float*)d_in[5];
    float* out = (float*)d_out;

    (void)in_sizes; (void)n_in; (void)out_size;

    static bool init_done = false;
    static void* gcounts_ptr = nullptr;
    if (!init_done) {
        cudaFuncSetAttribute(accum_kernel,
                             cudaFuncAttributeMaxDynamicSharedMemorySize, SMEM_BYTES);
        cudaGetSymbolAddress(&gcounts_ptr, g_counts);
        init_done = true;
    }

    // zero via memset nodes (cheaper than a kernel; graph-capturable)
    cudaMemsetAsync(out, 0, (size_t)BB * SS * CC * sizeof(float), 0);
    cudaMemsetAsync(gcounts_ptr, 0, (size_t)BB * SS * sizeof(float), 0);

    accum_kernel<<<NCTA, NTH, SMEM_BYTES>>>(feat, seg, out);

    const int n4 = BB * SS * CC / 4;
    finalize_kernel<<<(n4 + 255) / 256, 256>>>((float4*)out, centroid,
                                               (const float4*)posW, (const float4*)posb);
}